// round 7
// baseline (speedup 1.0000x reference)
#include <cuda_runtime.h>

#define EPSV   1e-7f
#define BB     64
#define DD     256
#define NSPLIT 16
#define TROWS  32                       // rows per tile
#define NTILES 8                        // 256 rows per CTA / TROWS
#define STAGES 3
#define TILE_F4 (TROWS * (DD/4))        // 2048 float4 per tile
#define SMEM_F4 (STAGES * TILE_F4)      // 96 KB dynamic smem

// Scratch (zero-initialized device globals; no allocations allowed).
__device__ float        g_part[BB * NSPLIT * DD];
__device__ float        g_zpart[BB * NSPLIT];
__device__ unsigned int g_cnt[BB];      // self-resetting ticket

__device__ __forceinline__ float tanh_approx(float v) {
    float r;
    asm("tanh.approx.f32 %0, %1;" : "=f"(r) : "f"(v));
    return r;
}

__device__ __forceinline__ void cp16(float4* dst, const float4* src) {
    unsigned s = (unsigned)__cvta_generic_to_shared(dst);
    asm volatile("cp.async.cg.shared.global [%0], [%1], 16;" :: "r"(s), "l"(src));
}
#define CP_COMMIT()  asm volatile("cp.async.commit_group;")
#define CP_WAIT(n)   asm volatile("cp.async.wait_group %0;" :: "n"(n))

#define DOT8(d, p0, p1)                \
    do {                               \
        d = (p0).x * w0.x;             \
        d = fmaf((p0).y, w0.y, d);     \
        d = fmaf((p0).z, w0.z, d);     \
        d = fmaf((p0).w, w0.w, d);     \
        d = fmaf((p1).x, w1.x, d);     \
        d = fmaf((p1).y, w1.y, d);     \
        d = fmaf((p1).z, w1.z, d);     \
        d = fmaf((p1).w, w1.w, d);     \
    } while (0)

#define ACC8(e, p0, p1)                \
    do {                               \
        acc0 = fmaf((p0).x, e, acc0);  \
        acc1 = fmaf((p0).y, e, acc1);  \
        acc2 = fmaf((p0).z, e, acc2);  \
        acc3 = fmaf((p0).w, e, acc3);  \
        acc4 = fmaf((p1).x, e, acc4);  \
        acc5 = fmaf((p1).y, e, acc5);  \
        acc6 = fmaf((p1).z, e, acc6);  \
        acc7 = fmaf((p1).w, e, acc7);  \
    } while (0)

// grid (B, NSPLIT), 256 threads = 8 warps. cp.async 3-stage pipeline.
__global__ void __launch_bounds__(256) attn_k(
    const float* __restrict__ x, const float* __restrict__ W,
    const float* __restrict__ bv, int T, float* __restrict__ out)
{
    extern __shared__ float4 smem[];              // STAGES * 32KB
    const int b    = blockIdx.x;
    const int sp   = blockIdx.y;
    const int tid  = threadIdx.x;
    const int lane = tid & 31;
    const int warp = tid >> 5;
    const int tileRows = NTILES * TROWS;          // 256
    const int t0   = sp * tileRows;

    const float4* xb = (const float4*)(x) + (size_t)b * T * (DD/4);

    // ---- prefetch STAGES tiles ----
    #pragma unroll
    for (int s = 0; s < STAGES; s++) {
        const float4* src = xb + (size_t)(t0 + s * TROWS) * (DD/4);
        float4* dst = smem + s * TILE_F4;
        #pragma unroll
        for (int j = 0; j < 8; j++)
            cp16(dst + tid + j * 256, src + tid + j * 256);
        CP_COMMIT();
    }

    const float4 w0 = __ldg((const float4*)W + lane);
    const float4 w1 = __ldg((const float4*)W + 32 + lane);

    float acc0=0.f, acc1=0.f, acc2=0.f, acc3=0.f;
    float acc4=0.f, acc5=0.f, acc6=0.f, acc7=0.f;
    float zloc = 0.f;

    for (int t = 0; t < NTILES; t++) {
        CP_WAIT(STAGES - 1);
        __syncthreads();

        const int slot = t % STAGES;
        const float4* rs = smem + slot * TILE_F4 + (warp * 4) * (DD/4);
        const int tg = t0 + t * TROWS + warp * 4;

        float4 a0 = rs[        lane];
        float4 a1 = rs[ 32  +  lane];
        float4 b0 = rs[ 64  +  lane];
        float4 b1 = rs[ 96  +  lane];
        float4 c0 = rs[128  +  lane];
        float4 c1 = rs[160  +  lane];
        float4 d0v= rs[192  +  lane];
        float4 d1v= rs[224  +  lane];

        float s0, s1, s2, s3;
        DOT8(s0, a0, a1);
        DOT8(s1, b0, b1);
        DOT8(s2, c0, c1);
        DOT8(s3, d0v, d1v);

        #pragma unroll
        for (int s = 16; s > 0; s >>= 1) {
            s0 += __shfl_xor_sync(0xffffffffu, s0, s);
            s1 += __shfl_xor_sync(0xffffffffu, s1, s);
            s2 += __shfl_xor_sync(0xffffffffu, s2, s);
            s3 += __shfl_xor_sync(0xffffffffu, s3, s);
        }

        const float e0 = __expf(tanh_approx(s0 + __ldg(bv + tg + 0)));
        const float e1 = __expf(tanh_approx(s1 + __ldg(bv + tg + 1)));
        const float e2 = __expf(tanh_approx(s2 + __ldg(bv + tg + 2)));
        const float e3 = __expf(tanh_approx(s3 + __ldg(bv + tg + 3)));
        zloc += (e0 + e1) + (e2 + e3);

        ACC8(e0, a0, a1);
        ACC8(e1, b0, b1);
        ACC8(e2, c0, c1);
        ACC8(e3, d0v, d1v);

        __syncthreads();   // all warps done reading slot before refill

        const int nt = t + STAGES;
        if (nt < NTILES) {
            const float4* src = xb + (size_t)(t0 + nt * TROWS) * (DD/4);
            float4* dst = smem + slot * TILE_F4;
            #pragma unroll
            for (int j = 0; j < 8; j++)
                cp16(dst + tid + j * 256, src + tid + j * 256);
        }
        CP_COMMIT();       // commit (possibly empty) to keep group accounting aligned
    }

    // ---- block reduction across 8 warps ----
    __shared__ float sacc[8][DD];
    __shared__ float sz[8];
    __shared__ int   s_last;
    const int j0 = lane * 4;
    sacc[warp][j0 + 0]       = acc0;
    sacc[warp][j0 + 1]       = acc1;
    sacc[warp][j0 + 2]       = acc2;
    sacc[warp][j0 + 3]       = acc3;
    sacc[warp][128 + j0 + 0] = acc4;
    sacc[warp][128 + j0 + 1] = acc5;
    sacc[warp][128 + j0 + 2] = acc6;
    sacc[warp][128 + j0 + 3] = acc7;
    if (lane == 0) sz[warp] = zloc;
    __syncthreads();

    float s = 0.f;
    #pragma unroll
    for (int w = 0; w < 8; w++) s += sacc[w][tid];
    g_part[(b * NSPLIT + sp) * DD + tid] = s;
    if (tid == 0) {
        float z = 0.f;
        #pragma unroll
        for (int w = 0; w < 8; w++) z += sz[w];
        g_zpart[b * NSPLIT + sp] = z;
    }

    __threadfence();
    __syncthreads();
    if (tid == 0) {
        unsigned int old = atomicAdd(&g_cnt[b], 1u);
        s_last = (old == NSPLIT - 1);
    }
    __syncthreads();

    if (s_last) {
        __threadfence();
        float tot = 0.f;
        #pragma unroll
        for (int s2 = 0; s2 < NSPLIT; s2++)
            tot += g_part[(b * NSPLIT + s2) * DD + tid];
        float z = 0.f;
        #pragma unroll
        for (int s2 = 0; s2 < NSPLIT; s2++)
            z += g_zpart[b * NSPLIT + s2];
        out[b * DD + tid] = tot / (z + EPSV);
        if (tid == 0) g_cnt[b] = 0;   // self-reset for graph replay
    }
}

extern "C" void kernel_launch(void* const* d_in, const int* in_sizes, int n_in,
                              void* d_out, int out_size) {
    const float* x  = (const float*)d_in[0];
    const float* W  = (const float*)d_in[1];
    const float* bv = (const float*)d_in[2];
    float* out = (float*)d_out;

    const int D = in_sizes[1];            // 256
    const int T = in_sizes[2];            // 4096
    const int B = in_sizes[0] / (T * D);  // 64

    const int dynSmem = SMEM_F4 * sizeof(float4);  // 96 KB
    static int attrSet = 0;
    if (!attrSet) {
        cudaFuncSetAttribute(attn_k, cudaFuncAttributeMaxDynamicSharedMemorySize, dynSmem);
        attrSet = 1;
    }

    dim3 grid(B, NSPLIT);
    attn_k<<<grid, 256, dynSmem>>>(x, W, bv, T, out);
}

// round 11
// speedup vs baseline: 1.3292x; 1.3292x over previous
#include <cuda_runtime.h>

#define EPSV   1e-7f
#define BB     64
#define DD     256
#define NSPLIT 32

// Scratch (zero-initialized device globals; no allocations allowed).
__device__ float        g_part[BB * NSPLIT * DD];
__device__ float        g_zpart[BB * NSPLIT];
__device__ unsigned int g_cnt[BB];      // self-resetting ticket

__device__ __forceinline__ float tanh_approx(float v) {
    float r;
    asm("tanh.approx.f32 %0, %1;" : "=f"(r) : "f"(v));
    return r;
}

#define DOT8(d, p0, p1)                \
    do {                               \
        d = (p0).x * w0.x;             \
        d = fmaf((p0).y, w0.y, d);     \
        d = fmaf((p0).z, w0.z, d);     \
        d = fmaf((p0).w, w0.w, d);     \
        d = fmaf((p1).x, w1.x, d);     \
        d = fmaf((p1).y, w1.y, d);     \
        d = fmaf((p1).z, w1.z, d);     \
        d = fmaf((p1).w, w1.w, d);     \
    } while (0)

#define ACC8(e, p0, p1)                \
    do {                               \
        acc0 = fmaf((p0).x, e, acc0);  \
        acc1 = fmaf((p0).y, e, acc1);  \
        acc2 = fmaf((p0).z, e, acc2);  \
        acc3 = fmaf((p0).w, e, acc3);  \
        acc4 = fmaf((p1).x, e, acc4);  \
        acc5 = fmaf((p1).y, e, acc5);  \
        acc6 = fmaf((p1).z, e, acc6);  \
        acc7 = fmaf((p1).w, e, acc7);  \
    } while (0)

// Compute scores + accumulate for 2 rows held in (A0,A1,B0,B1) at rows t, t+1.
#define COMPUTE2(A0, A1, B0, B1, trow)                                   \
    do {                                                                 \
        float s0, s1;                                                    \
        DOT8(s0, A0, A1);                                                \
        DOT8(s1, B0, B1);                                                \
        _Pragma("unroll")                                                \
        for (int sh = 16; sh > 0; sh >>= 1) {                            \
            s0 += __shfl_xor_sync(0xffffffffu, s0, sh);                  \
            s1 += __shfl_xor_sync(0xffffffffu, s1, sh);                  \
        }                                                                \
        const float e0 = __expf(tanh_approx(s0 + __ldg(bv + (trow))));   \
        const float e1 = __expf(tanh_approx(s1 + __ldg(bv + (trow)+1))); \
        zloc += e0 + e1;                                                 \
        ACC8(e0, A0, A1);                                                \
        ACC8(e1, B0, B1);                                                \
    } while (0)

// Load 2 rows (4 float4 per lane) from row index tr (clamped by caller).
#define LOAD2(A0, A1, B0, B1, tr)                                        \
    do {                                                                 \
        const float4* _r = xb + (size_t)(tr) * (DD/4);                   \
        A0 = __ldcs(_r +       lane);                                    \
        A1 = __ldcs(_r +  32 + lane);                                    \
        B0 = __ldcs(_r +  64 + lane);                                    \
        B1 = __ldcs(_r +  96 + lane);                                    \
    } while (0)

// grid (B, NSPLIT), block 256 = 8 warps.
// Each warp streams rowsPerWarp contiguous rows, 2 rows per step,
// register double-buffered: next step's loads issued before this step's math.
__global__ void __launch_bounds__(256, 4) attn_k(
    const float* __restrict__ x, const float* __restrict__ W,
    const float* __restrict__ bv, int T, int tileRows, float* __restrict__ out)
{
    const int b    = blockIdx.x;
    const int sp   = blockIdx.y;
    const int tid  = threadIdx.x;
    const int lane = tid & 31;
    const int warp = tid >> 5;
    const int rowsPerWarp = tileRows >> 3;            // 16
    const int t0   = sp * tileRows + warp * rowsPerWarp;

    const float4 w0 = __ldg((const float4*)W + lane);
    const float4 w1 = __ldg((const float4*)W + 32 + lane);

    float acc0=0.f, acc1=0.f, acc2=0.f, acc3=0.f;
    float acc4=0.f, acc5=0.f, acc6=0.f, acc7=0.f;
    float zloc = 0.f;

    const float4* xb = (const float4*)(x) + (size_t)b * T * (DD/4);

    float4 pA0, pA1, pB0, pB1;   // buffer P
    float4 qA0, qA1, qB0, qB1;   // buffer Q

    LOAD2(pA0, pA1, pB0, pB1, t0);

    // Unrolled by 2 steps (4 rows) per loop trip; rowsPerWarp = 16 -> 4 trips.
    #pragma unroll 2
    for (int i = 0; i < rowsPerWarp; i += 4) {
        const int t = t0 + i;
        // prefetch rows t+2,t+3 into Q, then compute P (rows t,t+1)
        LOAD2(qA0, qA1, qB0, qB1, t + 2);
        COMPUTE2(pA0, pA1, pB0, pB1, t);
        // prefetch rows t+4,t+5 into P (clamped at the end), compute Q
        int tn = t + 4;
        if (tn >= t0 + rowsPerWarp) tn = t0;          // harmless redundant load
        LOAD2(pA0, pA1, pB0, pB1, tn);
        COMPUTE2(qA0, qA1, qB0, qB1, t + 2);
    }

    // ---- block reduction across 8 warps ----
    __shared__ float sacc[8][DD];
    __shared__ float sz[8];
    __shared__ int   s_last;
    const int j0 = lane * 4;
    sacc[warp][j0 + 0]       = acc0;
    sacc[warp][j0 + 1]       = acc1;
    sacc[warp][j0 + 2]       = acc2;
    sacc[warp][j0 + 3]       = acc3;
    sacc[warp][128 + j0 + 0] = acc4;
    sacc[warp][128 + j0 + 1] = acc5;
    sacc[warp][128 + j0 + 2] = acc6;
    sacc[warp][128 + j0 + 3] = acc7;
    if (lane == 0) sz[warp] = zloc;
    __syncthreads();

    float s = 0.f;
    #pragma unroll
    for (int w = 0; w < 8; w++) s += sacc[w][tid];
    g_part[(b * NSPLIT + sp) * DD + tid] = s;
    if (tid == 0) {
        float z = 0.f;
        #pragma unroll
        for (int w = 0; w < 8; w++) z += sz[w];
        g_zpart[b * NSPLIT + sp] = z;
    }

    __threadfence();
    __syncthreads();
    if (tid == 0) {
        unsigned int old = atomicAdd(&g_cnt[b], 1u);
        s_last = (old == NSPLIT - 1);
    }
    __syncthreads();

    if (s_last) {
        __threadfence();
        float tot = 0.f;
        #pragma unroll
        for (int s2 = 0; s2 < NSPLIT; s2++)
            tot += g_part[(b * NSPLIT + s2) * DD + tid];
        float z = 0.f;
        #pragma unroll
        for (int s2 = 0; s2 < NSPLIT; s2++)
            z += g_zpart[b * NSPLIT + s2];
        out[b * DD + tid] = tot / (z + EPSV);
        if (tid == 0) g_cnt[b] = 0;   // self-reset for graph replay
    }
}

extern "C" void kernel_launch(void* const* d_in, const int* in_sizes, int n_in,
                              void* d_out, int out_size) {
    const float* x  = (const float*)d_in[0];
    const float* W  = (const float*)d_in[1];
    const float* bv = (const float*)d_in[2];
    float* out = (float*)d_out;

    const int D = in_sizes[1];            // 256
    const int T = in_sizes[2];            // 4096
    const int B = in_sizes[0] / (T * D);  // 64

    const int tileRows = T / NSPLIT;      // 128
    dim3 grid(B, NSPLIT);
    attn_k<<<grid, 256>>>(x, W, bv, T, tileRows, out);
}